// round 11
// baseline (speedup 1.0000x reference)
#include <cuda_runtime.h>

#define S_LEN 1024
#define NP 513
#define PSTR 516
#define OUT_ELEMS 4194304
#define NROWS 65536

typedef unsigned long long ull;

__device__ float g_C[(size_t)NROWS * PSTR];   // unnormalized shifted weights E

// packed fp32x2 FMA (sm_103a FFMA2 — only reachable via PTX)
__device__ __forceinline__ void ffma2(ull& d, ull a, ull b) {
    asm("fma.rn.f32x2 %0, %1, %2, %0;" : "+l"(d) : "l"(a), "l"(b));
}
__device__ __forceinline__ ull dup2(float x) {
    ull r;
    asm("mov.b64 %0, {%1, %1};" : "=l"(r) : "f"(x));
    return r;
}
__device__ __forceinline__ void unpk(float& lo, float& hi, ull v) {
    asm("mov.b64 {%0, %1}, %2;" : "=f"(lo), "=f"(hi) : "l"(v));
}

// ---------------------------------------------------------------------------
// Kernel A: bias(row, j) = q_row · Wk[clip(j-i)+512], written DIRECTLY into
// the weights buffer in (row, j) layout. 128x128 (r,p) tiles, FFMA2 8x8.
// ---------------------------------------------------------------------------
__global__ void __launch_bounds__(256) kernA(const float* __restrict__ q,
                                             const float* __restrict__ Wk,
                                             float* __restrict__ wbuf) {
    const int r0 = blockIdx.x * 128;
    const int p0 = blockIdx.y * 128;
    const int i0 = r0 & (S_LEN - 1);
    if (p0 + 127 < 385 - i0) return;   // whole tile maps to j < 0
    extern __shared__ float dsmA[];
    float (*sQT)[132] = (float(*)[132])(dsmA);          // [d][r]
    float (*sWT)[132] = (float(*)[132])(dsmA + 8448);   // [d][p-p0]
    const int tid = threadIdx.x;
    #pragma unroll
    for (int l = 0; l < 8; ++l) {
        int e = tid + l * 256;
        int r = e & 127, c4 = (e >> 7) << 2;
        float4 vv = *(const float4*)(q + (size_t)(r0 + r) * 64 + c4);
        sQT[c4+0][r]=vv.x; sQT[c4+1][r]=vv.y; sQT[c4+2][r]=vv.z; sQT[c4+3][r]=vv.w;
    }
    #pragma unroll
    for (int l = 0; l < 8; ++l) {
        int e = tid + l * 256;
        int r = e & 127, c4 = (e >> 7) << 2;
        int p = p0 + r;
        float4 vv = make_float4(0.f,0.f,0.f,0.f);
        if (p < NP) vv = *(const float4*)(Wk + (size_t)p * 64 + c4);
        sWT[c4+0][r]=vv.x; sWT[c4+1][r]=vv.y; sWT[c4+2][r]=vv.z; sWT[c4+3][r]=vv.w;
    }
    __syncthreads();
    const int tx = tid & 15, ty = tid >> 4;
    ull acc2[8][4] = {};
    #pragma unroll 4
    for (int d = 0; d < 64; ++d) {
        float4 a0 = *(const float4*)&sQT[d][4*ty];
        float4 a1 = *(const float4*)&sQT[d][4*ty + 64];
        ull b0 = *(const ull*)&sWT[d][4*tx];
        ull b1 = *(const ull*)&sWT[d][4*tx + 2];
        ull b2 = *(const ull*)&sWT[d][4*tx + 64];
        ull b3 = *(const ull*)&sWT[d][4*tx + 66];
        ull da[8] = {dup2(a0.x), dup2(a0.y), dup2(a0.z), dup2(a0.w),
                     dup2(a1.x), dup2(a1.y), dup2(a1.z), dup2(a1.w)};
        #pragma unroll
        for (int ri = 0; ri < 8; ++ri) {
            ffma2(acc2[ri][0], da[ri], b0);
            ffma2(acc2[ri][1], da[ri], b1);
            ffma2(acc2[ri][2], da[ri], b2);
            ffma2(acc2[ri][3], da[ri], b3);
        }
    }
    #pragma unroll
    for (int rs = 0; rs < 8; ++rs) {
        const int r = r0 + ((rs < 4) ? 4*ty + rs : 64 + 4*ty + rs - 4);
        const int i = r & (S_LEN - 1);
        const size_t wrow = (size_t)r * S_LEN;
        float o[8];
        unpk(o[0], o[1], acc2[rs][0]); unpk(o[2], o[3], acc2[rs][1]);
        unpk(o[4], o[5], acc2[rs][2]); unpk(o[6], o[7], acc2[rs][3]);
        #pragma unroll
        for (int t = 0; t < 4; ++t) {
            const int p  = p0 + 4*tx + t;
            const int j  = p + i - 512;
            if (j >= 0 && p <= 512) wbuf[wrow + j] = o[t];
            const int p2 = p + 64;
            const int j2 = p2 + i - 512;
            if (j2 >= 0 && p2 <= 512) wbuf[wrow + j2] = o[4+t];
        }
        if (p0 == 0) {
            // clipped region j < i-512: bias = P[i, 0] (tx==0's o[0])
            const float v0 = __shfl_sync(0xffffffffu, o[0], tid & 16, 32);
            for (int j = tx; j < i - 512; j += 16)
                wbuf[wrow + j] = v0;
        }
    }
}

// ---------------------------------------------------------------------------
// Fused B+C+D: pass1 flash loop (bias read from wbuf, coalesced) -> sInv ->
// in-CTA rel-val GEMM (L2-hot g_C) -> output write -> pass2 weights from g_C.
// ---------------------------------------------------------------------------
__global__ void __launch_bounds__(256) kernBCD(const float* __restrict__ q,
                                               const float* __restrict__ kmat,
                                               const float* __restrict__ v,
                                               const float* __restrict__ Wv,
                                               float* __restrict__ wbuf,
                                               float* __restrict__ outp) {
    extern __shared__ float dsm[];
    float (*sQT)[68] = (float(*)[68])(dsm);          // [d][r]
    float (*sKE)[68] = (float(*)[68])(dsm + 4352);   // K^T, then E^T, then C-chunk [m][r]
    float (*sV)[68]  = (float(*)[68])(dsm + 8704);   // V [j][d], then Wv_rev chunk [m][d]
    float *sS   = dsm + 13056;
    float *sCs  = dsm + 13120;
    float *sInv = dsm + 13184;

    const int bh = blockIdx.y;
    const int ib = 15 - (int)blockIdx.x;     // heavy blocks first
    const int i0 = ib * 64;
    const int rowbase = bh * S_LEN + i0;
    const int tid = threadIdx.x;
    const int tx = tid & 15, ty = tid >> 4;
    const int rl = ty << 2, cl = tx << 2;

    for (int e = tid; e < 1024; e += 256) {
        int r = e >> 4, c4 = (e & 15) << 2;
        float4 vv = *(const float4*)(q + (size_t)(rowbase + r) * 64 + c4);
        sQT[c4+0][r]=vv.x; sQT[c4+1][r]=vv.y; sQT[c4+2][r]=vv.z; sQT[c4+3][r]=vv.w;
    }
    if (tid < 64) { sS[tid] = 0.f; sCs[tid] = 0.f; }

    ull accO2[4][2] = {};

    // ---------------- pass1: flash loop ----------------
    for (int jb = 0; jb <= ib; ++jb) {
        const int j0 = jb * 64;
        __syncthreads();   // (1) prev E@V done: sKE, sV writable

        #pragma unroll
        for (int l = 0; l < 4; ++l) {
            int e = tid + l * 256;
            int r = e >> 4, c4 = (e & 15) << 2;
            float4 vv = *(const float4*)(kmat + (size_t)(bh*S_LEN + j0 + r)*64 + c4);
            sKE[c4+0][r]=vv.x; sKE[c4+1][r]=vv.y; sKE[c4+2][r]=vv.z; sKE[c4+3][r]=vv.w;
            *(float4*)&sV[r][c4] = *(const float4*)(v + (size_t)(bh*S_LEN + j0 + r)*64 + c4);
        }
        __syncthreads();   // (2) tiles ready

        // QK^T (FFMA2)
        ull accQ2[4][2] = {};
        #pragma unroll 8
        for (int d = 0; d < 64; ++d) {
            float4 a4 = *(const float4*)&sQT[d][rl];
            ull b01 = *(const ull*)&sKE[d][cl];
            ull b23 = *(const ull*)&sKE[d][cl + 2];
            ull d0 = dup2(a4.x), d1 = dup2(a4.y), d2 = dup2(a4.z), d3 = dup2(a4.w);
            ffma2(accQ2[0][0], d0, b01); ffma2(accQ2[0][1], d0, b23);
            ffma2(accQ2[1][0], d1, b01); ffma2(accQ2[1][1], d1, b23);
            ffma2(accQ2[2][0], d2, b01); ffma2(accQ2[2][1], d2, b23);
            ffma2(accQ2[3][0], d3, b01); ffma2(accQ2[3][1], d3, b23);
        }

        float accQ[4][4];
        #pragma unroll
        for (int ri = 0; ri < 4; ++ri) {
            unpk(accQ[ri][0], accQ[ri][1], accQ2[ri][0]);
            unpk(accQ[ri][2], accQ[ri][3], accQ2[ri][1]);
        }

        // bias (coalesced from wbuf) + mask + exp + rowsum + scatter
        #pragma unroll
        for (int ri = 0; ri < 4; ++ri) {
            const int r = rl + ri;
            const int i = i0 + r;
            const size_t wrow = (size_t)(rowbase + r) * S_LEN;
            const size_t prow = (size_t)(rowbase + r) * PSTR;
            float4 b4 = *(const float4*)(wbuf + wrow + j0 + cl);
            const float bb[4] = {b4.x, b4.y, b4.z, b4.w};
            #pragma unroll
            for (int ci = 0; ci < 4; ++ci) {
                const int j = j0 + cl + ci;
                float l = accQ[ri][ci] + bb[ci];
                if (j > i) l = -1e30f;
                accQ[ri][ci] = __expf(l);
            }
            float se = accQ[ri][0] + accQ[ri][1] + accQ[ri][2] + accQ[ri][3];
            #pragma unroll
            for (int off = 8; off >= 1; off >>= 1)
                se += __shfl_xor_sync(0xffffffffu, se, off);
            if (tx == 0) sS[r] += se;
            #pragma unroll
            for (int ci = 0; ci < 4; ++ci) {
                const int mm = i - (j0 + cl + ci);
                if (mm >= 0) {
                    if (mm < 512) {
                        g_C[prow + mm] = accQ[ri][ci];
                    } else {
                        atomicAdd(&sCs[r], accQ[ri][ci]);
                        // individual E unrecoverable from lumped slot -> raw to wbuf
                        wbuf[wrow + j0 + cl + ci] = accQ[ri][ci];
                    }
                }
            }
        }

        __syncthreads();   // (3) QK reads of sKE done -> overwrite with E^T
        #pragma unroll
        for (int ri = 0; ri < 4; ++ri)
            #pragma unroll
            for (int ci = 0; ci < 4; ++ci) sKE[cl + ci][rl + ri] = accQ[ri][ci];
        __syncthreads();   // (4) E^T ready

        // accO += E @ V (FFMA2)
        #pragma unroll 8
        for (int j = 0; j < 64; ++j) {
            float4 a4 = *(const float4*)&sKE[j][rl];
            ull b01 = *(const ull*)&sV[j][cl];
            ull b23 = *(const ull*)&sV[j][cl + 2];
            ull d0 = dup2(a4.x), d1 = dup2(a4.y), d2 = dup2(a4.z), d3 = dup2(a4.w);
            ffma2(accO2[0][0], d0, b01); ffma2(accO2[0][1], d0, b23);
            ffma2(accO2[1][0], d1, b01); ffma2(accO2[1][1], d1, b23);
            ffma2(accO2[2][0], d2, b01); ffma2(accO2[2][1], d2, b23);
            ffma2(accO2[3][0], d3, b01); ffma2(accO2[3][1], d3, b23);
        }
    }

    __syncthreads();
    if (tid < 64) {
        sInv[tid] = 1.0f / sS[tid];
        g_C[(size_t)(rowbase + tid) * PSTR + 512] = sCs[tid];
    }
    __syncthreads();

    // ---------------- D-phase: accO += C_E @ Wv_rev (L2-hot g_C) ----------------
    const int mEnd = min(NP, i0 + 64);
    for (int m0 = 0; m0 < mEnd; m0 += 64) {
        __syncthreads();   // chunk buffers free
        #pragma unroll
        for (int l = 0; l < 4; ++l) {
            int e = tid + l * 256;
            int r = e >> 4, c4 = (e & 15) << 2;
            const int mb = m0 + c4;
            const int irow = i0 + r;
            float4 vv = make_float4(0.f,0.f,0.f,0.f);
            if (mb <= 512)
                vv = *(const float4*)(g_C + (size_t)(rowbase + r)*PSTR + mb);
            float comp[4] = {vv.x, vv.y, vv.z, vv.w};
            #pragma unroll
            for (int t = 0; t < 4; ++t) {
                const int m = mb + t;
                const bool ok = (m < 512) ? (m <= irow) : (m == 512);
                sKE[c4 + t][r] = ok ? comp[t] : 0.f;
            }
        }
        #pragma unroll
        for (int l = 0; l < 4; ++l) {
            int e = tid + l * 256;
            int mm = e >> 4, c4 = (e & 15) << 2;
            const int m = m0 + mm;
            float4 vv = make_float4(0.f,0.f,0.f,0.f);
            if (m <= 512) vv = *(const float4*)(Wv + (size_t)(512 - m)*64 + c4);
            *(float4*)&sV[mm][c4] = vv;
        }
        __syncthreads();
        #pragma unroll 8
        for (int m = 0; m < 64; ++m) {
            float4 a4 = *(const float4*)&sKE[m][rl];
            ull b01 = *(const ull*)&sV[m][cl];
            ull b23 = *(const ull*)&sV[m][cl + 2];
            ull d0 = dup2(a4.x), d1 = dup2(a4.y), d2 = dup2(a4.z), d3 = dup2(a4.w);
            ffma2(accO2[0][0], d0, b01); ffma2(accO2[0][1], d0, b23);
            ffma2(accO2[1][0], d1, b01); ffma2(accO2[1][1], d1, b23);
            ffma2(accO2[2][0], d2, b01); ffma2(accO2[2][1], d2, b23);
            ffma2(accO2[3][0], d3, b01); ffma2(accO2[3][1], d3, b23);
        }
    }

    // final output: (E@V + C@Wv_rev) * sInv
    #pragma unroll
    for (int ri = 0; ri < 4; ++ri) {
        float o[4];
        unpk(o[0], o[1], accO2[ri][0]);
        unpk(o[2], o[3], accO2[ri][1]);
        const float inv = sInv[rl + ri];
        *(float4*)(outp + (size_t)(rowbase + rl + ri) * 64 + cl)
            = make_float4(o[0]*inv, o[1]*inv, o[2]*inv, o[3]*inv);
    }

    // ---------------- pass2: weights from g_C (L2-hot) ----------------
    for (int jb = 0; jb < 16; ++jb) {
        const int j0 = jb * 64;
        if (jb > ib) {
            const float4 z = make_float4(0.f, 0.f, 0.f, 0.f);
            for (int e = tid; e < 1024; e += 256) {
                int r = e >> 4, c4 = (e & 15) << 2;
                *(float4*)(wbuf + (size_t)(rowbase + r) * S_LEN + j0 + c4) = z;
            }
            continue;
        }
        for (int e = tid; e < 1024; e += 256) {
            int r = e >> 4, c4 = (e & 15) << 2;
            const int i = i0 + r;
            const size_t row = (size_t)(rowbase + r);
            const size_t addr = row * S_LEN + j0 + c4;
            const size_t prow = row * PSTR;
            const float f = sInv[r];
            float w[4];
            #pragma unroll
            for (int t = 0; t < 4; ++t) {
                const int j = j0 + c4 + t;
                const int mm = i - j;
                float eV = 0.f;
                if (mm >= 0) {
                    if (mm < 512) eV = g_C[prow + mm];
                    else          eV = wbuf[addr + t];   // raw E written in pass1
                }
                w[t] = eV * f;
            }
            *(float4*)(wbuf + addr) = make_float4(w[0], w[1], w[2], w[3]);
        }
    }
}

// ---------------------------------------------------------------------------
extern "C" void kernel_launch(void* const* d_in, const int* in_sizes, int n_in,
                              void* d_out, int out_size) {
    const float* q  = (const float*)d_in[0];
    const float* k  = (const float*)d_in[1];
    const float* v  = (const float*)d_in[2];
    const float* Wk = (const float*)d_in[3];
    const float* Wv = (const float*)d_in[4];

    float* outp = (float*)d_out;            // (B,H,S,D)
    float* wbuf = outp + OUT_ELEMS;         // (B,H,S,S) weights (bias staged here)

    static bool attrs_set = false;
    if (!attrs_set) {
        cudaFuncSetAttribute(kernA,   cudaFuncAttributeMaxDynamicSharedMemorySize, 67584);
        cudaFuncSetAttribute(kernBCD, cudaFuncAttributeMaxDynamicSharedMemorySize, 53248);
        attrs_set = true;
    }
    kernA<<<dim3(512, 5), 256, 67584>>>(q, Wk, wbuf);
    kernBCD<<<dim3(16, 64), 256, 53248>>>(q, k, v, Wv, wbuf, outp);
}

// round 12
// speedup vs baseline: 1.4174x; 1.4174x over previous
#include <cuda_runtime.h>
#include <cuda_bf16.h>

#define S_LEN 1024
#define NP 513
#define PSTR 516
#define OUT_ELEMS 4194304
#define NROWS 65536
#define TW 72   // bf16 smem row stride (elements)

typedef unsigned long long ull;
typedef unsigned int u32;

__device__ float g_P[(size_t)NROWS * PSTR];   // P[row,p] = q[row]·Wk[p]
__device__ float g_C[(size_t)NROWS * PSTR];   // unnormalized shifted weights E

// smem byte offsets for kernBCD
#define QH_OFF 0
#define QL_OFF 9216
#define KH_OFF 18432
#define KL_OFF 27648
#define VH_OFF 36864
#define VL_OFF 46080
#define EH_OFF 55296
#define EL_OFF 64512
#define SS_OFF 73728
#define SCS_OFF 73984
#define SINV_OFF 74240
#define SMEM_BCD 74496

// ---- scalar FFMA2 helpers (D-phase / kernA) ----
__device__ __forceinline__ void ffma2(ull& d, ull a, ull b) {
    asm("fma.rn.f32x2 %0, %1, %2, %0;" : "+l"(d) : "l"(a), "l"(b));
}
__device__ __forceinline__ ull dup2(float x) {
    ull r; asm("mov.b64 %0, {%1, %1};" : "=l"(r) : "f"(x)); return r;
}
__device__ __forceinline__ void unpk(float& lo, float& hi, ull v) {
    asm("mov.b64 {%0, %1}, %2;" : "=f"(lo), "=f"(hi) : "l"(v));
}

// ---- tensor helpers ----
__device__ __forceinline__ void ldmx4(u32* r, u32 addr) {
    asm volatile("ldmatrix.sync.aligned.m8n8.x4.shared.b16 {%0,%1,%2,%3}, [%4];"
        : "=r"(r[0]), "=r"(r[1]), "=r"(r[2]), "=r"(r[3]) : "r"(addr));
}
__device__ __forceinline__ void ldmx2(u32* r, u32 addr) {
    asm volatile("ldmatrix.sync.aligned.m8n8.x2.shared.b16 {%0,%1}, [%2];"
        : "=r"(r[0]), "=r"(r[1]) : "r"(addr));
}
__device__ __forceinline__ void ldmx2t(u32* r, u32 addr) {
    asm volatile("ldmatrix.sync.aligned.m8n8.x2.trans.shared.b16 {%0,%1}, [%2];"
        : "=r"(r[0]), "=r"(r[1]) : "r"(addr));
}
__device__ __forceinline__ void mma16816(float* c, const u32* a, const u32* b) {
    asm volatile("mma.sync.aligned.m16n8k16.row.col.f32.bf16.bf16.f32 "
        "{%0,%1,%2,%3}, {%4,%5,%6,%7}, {%8,%9}, {%0,%1,%2,%3};"
        : "+f"(c[0]), "+f"(c[1]), "+f"(c[2]), "+f"(c[3])
        : "r"(a[0]), "r"(a[1]), "r"(a[2]), "r"(a[3]), "r"(b[0]), "r"(b[1]));
}
// split two floats into packed bf16x2 hi and lo parts
__device__ __forceinline__ void split2(float x, float y, u32& h, u32& l) {
    __nv_bfloat16 hx = __float2bfloat16(x), hy = __float2bfloat16(y);
    __nv_bfloat162 hh; hh.x = hx; hh.y = hy;
    __nv_bfloat162 ll;
    ll.x = __float2bfloat16(x - __bfloat162float(hx));
    ll.y = __float2bfloat16(y - __bfloat162float(hy));
    h = *(u32*)&hh; l = *(u32*)&ll;
}

// ---------------------------------------------------------------------------
// Kernel A: P = Q @ Wk^T into g_P (round-10 proven version)
// ---------------------------------------------------------------------------
__global__ void __launch_bounds__(256) kernA(const float* __restrict__ q,
                                             const float* __restrict__ Wk) {
    const int r0 = blockIdx.x * 128;
    const int p0 = blockIdx.y * 128;
    const int i0 = r0 & (S_LEN - 1);
    if (p0 + 127 < 385 - i0) return;
    extern __shared__ float dsmA[];
    float (*sQT)[132] = (float(*)[132])(dsmA);
    float (*sWT)[132] = (float(*)[132])(dsmA + 8448);
    const int tid = threadIdx.x;
    #pragma unroll
    for (int l = 0; l < 8; ++l) {
        int e = tid + l * 256;
        int r = e & 127, c4 = (e >> 7) << 2;
        float4 vv = *(const float4*)(q + (size_t)(r0 + r) * 64 + c4);
        sQT[c4+0][r]=vv.x; sQT[c4+1][r]=vv.y; sQT[c4+2][r]=vv.z; sQT[c4+3][r]=vv.w;
    }
    #pragma unroll
    for (int l = 0; l < 8; ++l) {
        int e = tid + l * 256;
        int r = e & 127, c4 = (e >> 7) << 2;
        int p = p0 + r;
        float4 vv = make_float4(0.f,0.f,0.f,0.f);
        if (p < NP) vv = *(const float4*)(Wk + (size_t)p * 64 + c4);
        sWT[c4+0][r]=vv.x; sWT[c4+1][r]=vv.y; sWT[c4+2][r]=vv.z; sWT[c4+3][r]=vv.w;
    }
    __syncthreads();
    const int tx = tid & 15, ty = tid >> 4;
    ull acc2[8][4] = {};
    #pragma unroll 4
    for (int d = 0; d < 64; ++d) {
        float4 a0 = *(const float4*)&sQT[d][4*ty];
        float4 a1 = *(const float4*)&sQT[d][4*ty + 64];
        ull b0 = *(const ull*)&sWT[d][4*tx];
        ull b1 = *(const ull*)&sWT[d][4*tx + 2];
        ull b2 = *(const ull*)&sWT[d][4*tx + 64];
        ull b3 = *(const ull*)&sWT[d][4*tx + 66];
        ull da[8] = {dup2(a0.x), dup2(a0.y), dup2(a0.z), dup2(a0.w),
                     dup2(a1.x), dup2(a1.y), dup2(a1.z), dup2(a1.w)};
        #pragma unroll
        for (int ri = 0; ri < 8; ++ri) {
            ffma2(acc2[ri][0], da[ri], b0);
            ffma2(acc2[ri][1], da[ri], b1);
            ffma2(acc2[ri][2], da[ri], b2);
            ffma2(acc2[ri][3], da[ri], b3);
        }
    }
    #pragma unroll
    for (int rs = 0; rs < 8; ++rs) {
        const int r = r0 + ((rs < 4) ? 4*ty + rs : 64 + 4*ty + rs - 4);
        const size_t row = (size_t)r * PSTR;
        float o[8];
        unpk(o[0], o[1], acc2[rs][0]); unpk(o[2], o[3], acc2[rs][1]);
        unpk(o[4], o[5], acc2[rs][2]); unpk(o[6], o[7], acc2[rs][3]);
        const int c0 = p0 + 4*tx;
        if (c0 <= 512)
            *(float4*)(g_P + row + c0) = make_float4(o[0],o[1],o[2],o[3]);
        const int c1 = p0 + 64 + 4*tx;
        if (c1 <= 512)
            *(float4*)(g_P + row + c1) = make_float4(o[4],o[5],o[6],o[7]);
    }
}

// ---------------------------------------------------------------------------
// Fused B+C+D: tensor-core (bf16 3-split mma) QK^T and E@V; scalar epilogues.
// ---------------------------------------------------------------------------
__global__ void __launch_bounds__(256) kernBCD(const float* __restrict__ q,
                                               const float* __restrict__ kmat,
                                               const float* __restrict__ v,
                                               const float* __restrict__ Wv,
                                               float* __restrict__ wbuf,
                                               float* __restrict__ outp) {
    extern __shared__ char smem[];
    __nv_bfloat16* Qh = (__nv_bfloat16*)(smem + QH_OFF);
    __nv_bfloat16* Ql = (__nv_bfloat16*)(smem + QL_OFF);
    __nv_bfloat16* Kh = (__nv_bfloat16*)(smem + KH_OFF);
    __nv_bfloat16* Kl = (__nv_bfloat16*)(smem + KL_OFF);
    __nv_bfloat16* Vh = (__nv_bfloat16*)(smem + VH_OFF);
    __nv_bfloat16* Vl = (__nv_bfloat16*)(smem + VL_OFF);
    __nv_bfloat16* Eh = (__nv_bfloat16*)(smem + EH_OFF);
    __nv_bfloat16* El = (__nv_bfloat16*)(smem + EL_OFF);
    float* sS   = (float*)(smem + SS_OFF);
    float* sCs  = (float*)(smem + SCS_OFF);
    float* sInv = (float*)(smem + SINV_OFF);
    const u32 sbase = (u32)__cvta_generic_to_shared(smem);

    const int bh = blockIdx.y;
    const int ib = 15 - (int)blockIdx.x;
    const int i0 = ib * 64;
    const int rowbase = bh * S_LEN + i0;
    const int tid = threadIdx.x;
    const int wid = tid >> 5, lane = tid & 31;
    const int mrow = 16 * (wid & 3);     // warp's m-tile rows
    const int n0   = 32 * (wid >> 2);    // warp's n-half cols
    const int tx = tid & 15, ty = tid >> 4;
    const int rl = ty << 2, cl = tx << 2;

    // ---- Q prep: split into Qh/Ql ----
    #pragma unroll
    for (int l = 0; l < 4; ++l) {
        int e = tid + l * 256;
        int r = e >> 4, c4 = (e & 15) << 2;
        float4 vv = *(const float4*)(q + (size_t)(rowbase + r) * 64 + c4);
        u32 h0, l0, h1, l1;
        split2(vv.x, vv.y, h0, l0); split2(vv.z, vv.w, h1, l1);
        *(u32*)&Qh[r*TW + c4] = h0; *(u32*)&Qh[r*TW + c4 + 2] = h1;
        *(u32*)&Ql[r*TW + c4] = l0; *(u32*)&Ql[r*TW + c4 + 2] = l1;
    }
    if (tid < 64) { sS[tid] = 0.f; sCs[tid] = 0.f; }

    // fragment-lane constants
    const int r1 = mrow + (lane >> 2), r2 = r1 + 8;
    const int i1 = i0 + r1, i2 = i0 + r2;
    const size_t prow1 = (size_t)(rowbase + r1) * PSTR;
    const size_t prow2 = (size_t)(rowbase + r2) * PSTR;
    const size_t wrow1 = (size_t)(rowbase + r1) * S_LEN;
    const size_t wrow2 = (size_t)(rowbase + r2) * S_LEN;

    // ldmatrix lane addresses (element offsets added per use)
    const int lA_r = (lane & 7) + ((lane >> 3) & 1) * 8;   // A rows (+8 matrices)
    const int lA_c = ((lane >> 4) & 1) * 8;                // A col half
    const int lB_r = (lane & 7);                           // B rows
    const int lB_c = ((lane >> 3) & 1) * 8;                // B col half (non-trans)
    const int lBt_r = (lane & 7) + ((lane >> 3) & 1) * 8;  // B rows (trans)

    float accO[4][4] = {};   // E@V accumulators (persist across tiles)

    // ================= pass1 =================
    for (int jb = 0; jb <= ib; ++jb) {
        const int j0 = jb * 64;
        __syncthreads();   // (1) previous tile's mma reads done

        // load K,V fp32 -> split -> smem bf16
        #pragma unroll
        for (int l = 0; l < 4; ++l) {
            int e = tid + l * 256;
            int r = e >> 4, c4 = (e & 15) << 2;
            float4 kv = *(const float4*)(kmat + (size_t)(bh*S_LEN + j0 + r)*64 + c4);
            u32 h0, l0, h1, l1;
            split2(kv.x, kv.y, h0, l0); split2(kv.z, kv.w, h1, l1);
            *(u32*)&Kh[r*TW + c4] = h0; *(u32*)&Kh[r*TW + c4 + 2] = h1;
            *(u32*)&Kl[r*TW + c4] = l0; *(u32*)&Kl[r*TW + c4 + 2] = l1;
            float4 vv = *(const float4*)(v + (size_t)(bh*S_LEN + j0 + r)*64 + c4);
            split2(vv.x, vv.y, h0, l0); split2(vv.z, vv.w, h1, l1);
            *(u32*)&Vh[r*TW + c4] = h0; *(u32*)&Vh[r*TW + c4 + 2] = h1;
            *(u32*)&Vl[r*TW + c4] = l0; *(u32*)&Vl[r*TW + c4 + 2] = l1;
        }
        __syncthreads();   // (2) tiles ready

        // ---- QK^T via mma ----
        float accC[4][4] = {};
        #pragma unroll
        for (int ks = 0; ks < 4; ++ks) {
            u32 ah[4], al[4], bh2[2], bl2[2];
            ldmx4(ah, sbase + QH_OFF + (u32)((mrow + lA_r)*TW + ks*16 + lA_c)*2);
            ldmx4(al, sbase + QL_OFF + (u32)((mrow + lA_r)*TW + ks*16 + lA_c)*2);
            #pragma unroll
            for (int nt = 0; nt < 4; ++nt) {
                ldmx2(bh2, sbase + KH_OFF + (u32)((n0 + 8*nt + lB_r)*TW + ks*16 + lB_c)*2);
                ldmx2(bl2, sbase + KL_OFF + (u32)((n0 + 8*nt + lB_r)*TW + ks*16 + lB_c)*2);
                mma16816(accC[nt], ah, bh2);
                mma16816(accC[nt], ah, bl2);
                mma16816(accC[nt], al, bh2);
            }
        }

        // ---- bias + mask + exp + rowsum + scatter + E->bf16 smem ----
        float s1 = 0.f, s2 = 0.f;
        #pragma unroll
        for (int nt = 0; nt < 4; ++nt) {
            const int jl = n0 + 8*nt + 2*(lane & 3);
            const int j  = j0 + jl;
            // row r1 (elements c0, c1)
            {
                int p0c = j - i1 + 512;   if (p0c < 0) p0c = 0;
                int p1c = j + 1 - i1 + 512; if (p1c < 0) p1c = 0;
                float l0 = accC[nt][0] + g_P[prow1 + p0c];
                float l1 = accC[nt][1] + g_P[prow1 + p1c];
                if (j     > i1) l0 = -1e30f;
                if (j + 1 > i1) l1 = -1e30f;
                float e0 = __expf(l0), e1 = __expf(l1);
                s1 += e0 + e1;
                int mm = i1 - j;
                if (mm >= 0) {
                    if (mm < 512) g_C[prow1 + mm] = e0;
                    else { atomicAdd(&sCs[r1], e0); wbuf[wrow1 + j] = e0; }
                }
                if (mm - 1 >= 0) {
                    if (mm - 1 < 512) g_C[prow1 + mm - 1] = e1;
                    else { atomicAdd(&sCs[r1], e1); wbuf[wrow1 + j + 1] = e1; }
                }
                u32 hh, ll; split2(e0, e1, hh, ll);
                *(u32*)&Eh[r1*TW + jl] = hh;
                *(u32*)&El[r1*TW + jl] = ll;
            }
            // row r2 (elements c2, c3)
            {
                int p0c = j - i2 + 512;   if (p0c < 0) p0c = 0;
                int p1c = j + 1 - i2 + 512; if (p1c < 0) p1c = 0;
                float l0 = accC[nt][2] + g_P[prow2 + p0c];
                float l1 = accC[nt][3] + g_P[prow2 + p1c];
                if (j     > i2) l0 = -1e30f;
                if (j + 1 > i2) l1 = -1e30f;
                float e0 = __expf(l0), e1 = __expf(l1);
                s2 += e0 + e1;
                int mm = i2 - j;
                if (mm >= 0) {
                    if (mm < 512) g_C[prow2 + mm] = e0;
                    else { atomicAdd(&sCs[r2], e0); wbuf[wrow2 + j] = e0; }
                }
                if (mm - 1 >= 0) {
                    if (mm - 1 < 512) g_C[prow2 + mm - 1] = e1;
                    else { atomicAdd(&sCs[r2], e1); wbuf[wrow2 + j + 1] = e1; }
                }
                u32 hh, ll; split2(e0, e1, hh, ll);
                *(u32*)&Eh[r2*TW + jl] = hh;
                *(u32*)&El[r2*TW + jl] = ll;
            }
        }
        s1 += __shfl_xor_sync(0xffffffffu, s1, 1);
        s1 += __shfl_xor_sync(0xffffffffu, s1, 2);
        s2 += __shfl_xor_sync(0xffffffffu, s2, 1);
        s2 += __shfl_xor_sync(0xffffffffu, s2, 2);
        if ((lane & 3) == 0) { atomicAdd(&sS[r1], s1); atomicAdd(&sS[r2], s2); }

        __syncthreads();   // (3) E tiles ready

        // ---- accO += E @ V via mma ----
        #pragma unroll
        for (int ks = 0; ks < 4; ++ks) {
            u32 ah[4], al[4], bh2[2], bl2[2];
            ldmx4(ah, sbase + EH_OFF + (u32)((mrow + lA_r)*TW + ks*16 + lA_c)*2);
            ldmx4(al, sbase + EL_OFF + (u32)((mrow + lA_r)*TW + ks*16 + lA_c)*2);
            #pragma unroll
            for (int nt = 0; nt < 4; ++nt) {
                ldmx2t(bh2, sbase + VH_OFF + (u32)((ks*16 + lBt_r)*TW + n0 + 8*nt)*2);
                ldmx2t(bl2, sbase + VL_OFF + (u32)((ks*16 + lBt_r)*TW + n0 + 8*nt)*2);
                mma16816(accO[nt], ah, bh2);
                mma16816(accO[nt], ah, bl2);
                mma16816(accO[nt], al, bh2);
            }
        }
    }

    __syncthreads();
    if (tid < 64) {
        sInv[tid] = 1.0f / sS[tid];
        g_C[(size_t)(rowbase + tid) * PSTR + 512] = sCs[tid];
    }
    // dump accO fragments -> sOut (fp32 64x68, aliases Kh/Kl region)
    float* sOut = (float*)(smem + KH_OFF);
    #pragma unroll
    for (int nt = 0; nt < 4; ++nt) {
        const int c = n0 + 8*nt + 2*(lane & 3);
        sOut[r1*68 + c]     = accO[nt][0];
        sOut[r1*68 + c + 1] = accO[nt][1];
        sOut[r2*68 + c]     = accO[nt][2];
        sOut[r2*68 + c + 1] = accO[nt][3];
    }

    // ---- D-phase (scalar FFMA2): accD += C_E @ Wv_rev, L2-hot g_C ----
    float* sCT = (float*)(smem + VH_OFF);   // [m][r] 64x68 (aliases Vh/Vl)
    float* sB  = (float*)(smem + EH_OFF);   // [m][d] 64x68 (aliases Eh/El)
    ull accD2[4][2] = {};
    const int mEnd = min(NP, i0 + 64);
    for (int m0 = 0; m0 < mEnd; m0 += 64) {
        __syncthreads();
        #pragma unroll
        for (int l = 0; l < 4; ++l) {
            int e = tid + l * 256;
            int r = e >> 4, c4 = (e & 15) << 2;
            const int mb = m0 + c4;
            const int irow = i0 + r;
            float4 vv = make_float4(0.f,0.f,0.f,0.f);
            if (mb <= 512)
                vv = *(const float4*)(g_C + (size_t)(rowbase + r)*PSTR + mb);
            float comp[4] = {vv.x, vv.y, vv.z, vv.w};
            #pragma unroll
            for (int t = 0; t < 4; ++t) {
                const int m = mb + t;
                const bool ok = (m < 512) ? (m <= irow) : (m == 512);
                sCT[(c4 + t)*68 + r] = ok ? comp[t] : 0.f;
            }
        }
        #pragma unroll
        for (int l = 0; l < 4; ++l) {
            int e = tid + l * 256;
            int mm = e >> 4, c4 = (e & 15) << 2;
            const int m = m0 + mm;
            float4 vv = make_float4(0.f,0.f,0.f,0.f);
            if (m <= 512) vv = *(const float4*)(Wv + (size_t)(512 - m)*64 + c4);
            *(float4*)&sB[mm*68 + c4] = vv;
        }
        __syncthreads();
        #pragma unroll 8
        for (int m = 0; m < 64; ++m) {
            float4 a4 = *(const float4*)&sCT[m*68 + rl];
            ull b01 = *(const ull*)&sB[m*68 + cl];
            ull b23 = *(const ull*)&sB[m*68 + cl + 2];
            ull d0 = dup2(a4.x), d1 = dup2(a4.y), d2 = dup2(a4.z), d3 = dup2(a4.w);
            ffma2(accD2[0][0], d0, b01); ffma2(accD2[0][1], d0, b23);
            ffma2(accD2[1][0], d1, b01); ffma2(accD2[1][1], d1, b23);
            ffma2(accD2[2][0], d2, b01); ffma2(accD2[2][1], d2, b23);
            ffma2(accD2[3][0], d3, b01); ffma2(accD2[3][1], d3, b23);
        }
    }

    // final output: (E@V + C@Wv_rev) * sInv
    #pragma unroll
    for (int ri = 0; ri < 4; ++ri) {
        float d0, d1, d2, d3;
        unpk(d0, d1, accD2[ri][0]);
        unpk(d2, d3, accD2[ri][1]);
        float4 o = *(const float4*)&sOut[(rl + ri)*68 + cl];
        const float inv = sInv[rl + ri];
        *(float4*)(outp + (size_t)(rowbase + rl + ri) * 64 + cl)
            = make_float4((o.x + d0)*inv, (o.y + d1)*inv, (o.z + d2)*inv, (o.w + d3)*inv);
    }

    // ---- pass2: weights from g_C (L2-hot) ----
    for (int jb = 0; jb < 16; ++jb) {
        const int j0 = jb * 64;
        if (jb > ib) {
            const float4 z = make_float4(0.f, 0.f, 0.f, 0.f);
            for (int e = tid; e < 1024; e += 256) {
                int r = e >> 4, c4 = (e & 15) << 2;
                *(float4*)(wbuf + (size_t)(rowbase + r) * S_LEN + j0 + c4) = z;
            }
            continue;
        }
        for (int e = tid; e < 1024; e += 256) {
            int r = e >> 4, c4 = (e & 15) << 2;
            const int i = i0 + r;
            const size_t row = (size_t)(rowbase + r);
            const size_t addr = row * S_LEN + j0 + c4;
            const size_t prow = row * PSTR;
            const float f = sInv[r];
            float w[4];
            #pragma unroll
            for (int t = 0; t < 4; ++t) {
                const int j = j0 + c4 + t;
                const int mm = i - j;
                float eV = 0.f;
                if (mm >= 0) {
                    if (mm < 512) eV = g_C[prow + mm];
                    else          eV = wbuf[addr + t];
                }
                w[t] = eV * f;
            }
            *(float4*)(wbuf + addr) = make_float4(w[0], w[1], w[2], w[3]);
        }
    }
}

// ---------------------------------------------------------------------------
extern "C" void kernel_launch(void* const* d_in, const int* in_sizes, int n_in,
                              void* d_out, int out_size) {
    const float* q  = (const float*)d_in[0];
    const float* k  = (const float*)d_in[1];
    const float* v  = (const float*)d_in[2];
    const float* Wk = (const float*)d_in[3];
    const float* Wv = (const float*)d_in[4];

    float* outp = (float*)d_out;            // (B,H,S,D)
    float* wbuf = outp + OUT_ELEMS;         // (B,H,S,S) weights

    static bool attrs_set = false;
    if (!attrs_set) {
        cudaFuncSetAttribute(kernA,   cudaFuncAttributeMaxDynamicSharedMemorySize, 67584);
        cudaFuncSetAttribute(kernBCD, cudaFuncAttributeMaxDynamicSharedMemorySize, SMEM_BCD);
        attrs_set = true;
    }
    kernA<<<dim3(512, 5), 256, 67584>>>(q, Wk);
    kernBCD<<<dim3(16, 64), 256, SMEM_BCD>>>(q, k, v, Wv, wbuf, outp);
}

// round 13
// speedup vs baseline: 1.5522x; 1.0951x over previous
#include <cuda_runtime.h>
#include <cuda_bf16.h>

#define S_LEN 1024
#define NP 513
#define PSTR 516
#define OUT_ELEMS 4194304
#define NROWS 65536
#define TW 72   // bf16 smem row stride (elements)

typedef unsigned long long ull;
typedef unsigned int u32;

__device__ float g_P[(size_t)NROWS * PSTR];   // P[row,p] = q[row]·Wk[p]
__device__ float g_C[(size_t)NROWS * PSTR];   // unnormalized shifted weights E
__device__ __nv_bfloat16 gKh[OUT_ELEMS], gKl[OUT_ELEMS];
__device__ __nv_bfloat16 gVh[OUT_ELEMS], gVl[OUT_ELEMS];

// smem byte offsets for kernBCD
#define QH_OFF 0
#define QL_OFF 9216
#define KH_OFF 18432
#define KL_OFF 27648
#define VH_OFF 36864
#define VL_OFF 46080
#define EH_OFF 55296
#define EL_OFF 64512
#define SS_OFF 73728
#define SCS_OFF 73984
#define SINV_OFF 74240
#define SMEM_BCD 74496

// smem byte offsets for kernA (tensor)
#define AQH_OFF 0
#define AQL_OFF 9216
#define AWH_OFF 18432
#define AWL_OFF 36864
#define SMEM_A 55296

// ---- scalar FFMA2 helpers ----
__device__ __forceinline__ void ffma2(ull& d, ull a, ull b) {
    asm("fma.rn.f32x2 %0, %1, %2, %0;" : "+l"(d) : "l"(a), "l"(b));
}
__device__ __forceinline__ ull dup2(float x) {
    ull r; asm("mov.b64 %0, {%1, %1};" : "=l"(r) : "f"(x)); return r;
}
__device__ __forceinline__ void unpk(float& lo, float& hi, ull v) {
    asm("mov.b64 {%0, %1}, %2;" : "=f"(lo), "=f"(hi) : "l"(v));
}

// ---- tensor helpers ----
__device__ __forceinline__ void ldmx4(u32* r, u32 addr) {
    asm volatile("ldmatrix.sync.aligned.m8n8.x4.shared.b16 {%0,%1,%2,%3}, [%4];"
        : "=r"(r[0]), "=r"(r[1]), "=r"(r[2]), "=r"(r[3]) : "r"(addr));
}
__device__ __forceinline__ void ldmx2(u32* r, u32 addr) {
    asm volatile("ldmatrix.sync.aligned.m8n8.x2.shared.b16 {%0,%1}, [%2];"
        : "=r"(r[0]), "=r"(r[1]) : "r"(addr));
}
__device__ __forceinline__ void ldmx2t(u32* r, u32 addr) {
    asm volatile("ldmatrix.sync.aligned.m8n8.x2.trans.shared.b16 {%0,%1}, [%2];"
        : "=r"(r[0]), "=r"(r[1]) : "r"(addr));
}
__device__ __forceinline__ void mma16816(float* c, const u32* a, const u32* b) {
    asm volatile("mma.sync.aligned.m16n8k16.row.col.f32.bf16.bf16.f32 "
        "{%0,%1,%2,%3}, {%4,%5,%6,%7}, {%8,%9}, {%0,%1,%2,%3};"
        : "+f"(c[0]), "+f"(c[1]), "+f"(c[2]), "+f"(c[3])
        : "r"(a[0]), "r"(a[1]), "r"(a[2]), "r"(a[3]), "r"(b[0]), "r"(b[1]));
}
__device__ __forceinline__ void split2(float x, float y, u32& h, u32& l) {
    __nv_bfloat16 hx = __float2bfloat16(x), hy = __float2bfloat16(y);
    __nv_bfloat162 hh; hh.x = hx; hh.y = hy;
    __nv_bfloat162 ll;
    ll.x = __float2bfloat16(x - __bfloat162float(hx));
    ll.y = __float2bfloat16(y - __bfloat162float(hy));
    h = *(u32*)&hh; l = *(u32*)&ll;
}

// ---------------------------------------------------------------------------
// kernSplit: K,V fp32 -> global bf16 hi/lo (once)
// ---------------------------------------------------------------------------
__global__ void __launch_bounds__(256) kernSplit(const float* __restrict__ k,
                                                 const float* __restrict__ v) {
    const int idx = (blockIdx.x * 256 + threadIdx.x) * 4;
    float4 kv = *(const float4*)(k + idx);
    u32 h0, l0, h1, l1;
    split2(kv.x, kv.y, h0, l0); split2(kv.z, kv.w, h1, l1);
    *(uint2*)&gKh[idx] = make_uint2(h0, h1);
    *(uint2*)&gKl[idx] = make_uint2(l0, l1);
    float4 vv = *(const float4*)(v + idx);
    split2(vv.x, vv.y, h0, l0); split2(vv.z, vv.w, h1, l1);
    *(uint2*)&gVh[idx] = make_uint2(h0, h1);
    *(uint2*)&gVl[idx] = make_uint2(l0, l1);
}

// ---------------------------------------------------------------------------
// kernP512: g_P[row, 512] = q[row] · Wk[512]  (fp32 exact; diagonal bias)
// ---------------------------------------------------------------------------
__global__ void __launch_bounds__(256) kernP512(const float* __restrict__ q,
                                                const float* __restrict__ Wk) {
    __shared__ float w512[64];
    const int tid = threadIdx.x;
    if (tid < 64) w512[tid] = Wk[(size_t)512 * 64 + tid];
    __syncthreads();
    const int row = blockIdx.x * 256 + tid;
    const float* qr = q + (size_t)row * 64;
    float s = 0.f;
    #pragma unroll
    for (int c4 = 0; c4 < 64; c4 += 4) {
        float4 vv = *(const float4*)(qr + c4);
        s += vv.x * w512[c4] + vv.y * w512[c4+1] + vv.z * w512[c4+2] + vv.w * w512[c4+3];
    }
    g_P[(size_t)row * PSTR + 512] = s;
}

// ---------------------------------------------------------------------------
// Kernel A (tensor): P = Q @ Wk^T for p in [0,512), 64x128 tiles, bf16 3-split
// ---------------------------------------------------------------------------
__global__ void __launch_bounds__(256) kernA(const float* __restrict__ q,
                                             const float* __restrict__ Wk) {
    const int r0 = blockIdx.x * 64;
    const int p0 = blockIdx.y * 128;
    const int i0 = r0 & (S_LEN - 1);
    if (p0 + 127 < 449 - i0) return;   // tile entirely below min needed p
    extern __shared__ char smemA[];
    __nv_bfloat16* Qh = (__nv_bfloat16*)(smemA + AQH_OFF);
    __nv_bfloat16* Ql = (__nv_bfloat16*)(smemA + AQL_OFF);
    __nv_bfloat16* Wh = (__nv_bfloat16*)(smemA + AWH_OFF);
    __nv_bfloat16* Wl = (__nv_bfloat16*)(smemA + AWL_OFF);
    const u32 sbase = (u32)__cvta_generic_to_shared(smemA);
    const int tid = threadIdx.x;
    const int wid = tid >> 5, lane = tid & 31;

    #pragma unroll
    for (int l = 0; l < 4; ++l) {
        int e = tid + l * 256;
        int r = e >> 4, c4 = (e & 15) << 2;
        float4 vv = *(const float4*)(q + (size_t)(r0 + r) * 64 + c4);
        u32 h0, l0, h1, l1;
        split2(vv.x, vv.y, h0, l0); split2(vv.z, vv.w, h1, l1);
        *(u32*)&Qh[r*TW + c4] = h0; *(u32*)&Qh[r*TW + c4 + 2] = h1;
        *(u32*)&Ql[r*TW + c4] = l0; *(u32*)&Ql[r*TW + c4 + 2] = l1;
    }
    #pragma unroll
    for (int l = 0; l < 8; ++l) {
        int e = tid + l * 256;
        int r = e >> 4, c4 = (e & 15) << 2;   // r 0..127, p = p0+r <= 511
        float4 vv = *(const float4*)(Wk + (size_t)(p0 + r) * 64 + c4);
        u32 h0, l0, h1, l1;
        split2(vv.x, vv.y, h0, l0); split2(vv.z, vv.w, h1, l1);
        *(u32*)&Wh[r*TW + c4] = h0; *(u32*)&Wh[r*TW + c4 + 2] = h1;
        *(u32*)&Wl[r*TW + c4] = l0; *(u32*)&Wl[r*TW + c4 + 2] = l1;
    }
    __syncthreads();

    const int mrow = 16 * (wid & 3);
    const int n0   = 64 * (wid >> 2);
    const int lA_r = (lane & 7) + ((lane >> 3) & 1) * 8;
    const int lA_c = ((lane >> 4) & 1) * 8;
    const int lB_r = (lane & 7);
    const int lB_c = ((lane >> 3) & 1) * 8;

    float accP[8][4] = {};
    #pragma unroll
    for (int ks = 0; ks < 4; ++ks) {
        u32 ah[4], al[4], bh2[2], bl2[2];
        ldmx4(ah, sbase + AQH_OFF + (u32)((mrow + lA_r)*TW + ks*16 + lA_c)*2);
        ldmx4(al, sbase + AQL_OFF + (u32)((mrow + lA_r)*TW + ks*16 + lA_c)*2);
        #pragma unroll
        for (int nt = 0; nt < 8; ++nt) {
            ldmx2(bh2, sbase + AWH_OFF + (u32)((n0 + 8*nt + lB_r)*TW + ks*16 + lB_c)*2);
            ldmx2(bl2, sbase + AWL_OFF + (u32)((n0 + 8*nt + lB_r)*TW + ks*16 + lB_c)*2);
            mma16816(accP[nt], ah, bh2);
            mma16816(accP[nt], ah, bl2);
            mma16816(accP[nt], al, bh2);
        }
    }

    const int r1 = mrow + (lane >> 2), r2 = r1 + 8;
    const size_t row1 = (size_t)(r0 + r1) * PSTR;
    const size_t row2 = (size_t)(r0 + r2) * PSTR;
    #pragma unroll
    for (int nt = 0; nt < 8; ++nt) {
        const int p = p0 + n0 + 8*nt + 2*(lane & 3);   // p <= 510, pairs valid
        *(float2*)(g_P + row1 + p) = make_float2(accP[nt][0], accP[nt][1]);
        *(float2*)(g_P + row2 + p) = make_float2(accP[nt][2], accP[nt][3]);
    }
}

// ---------------------------------------------------------------------------
// Fused B+C+D: tensor-core QK^T and E@V (pre-split K/V); scalar epilogues.
// ---------------------------------------------------------------------------
__global__ void __launch_bounds__(256) kernBCD(const float* __restrict__ q,
                                               const float* __restrict__ Wv,
                                               float* __restrict__ wbuf,
                                               float* __restrict__ outp) {
    extern __shared__ char smem[];
    __nv_bfloat16* Qh = (__nv_bfloat16*)(smem + QH_OFF);
    __nv_bfloat16* Ql = (__nv_bfloat16*)(smem + QL_OFF);
    __nv_bfloat16* Kh = (__nv_bfloat16*)(smem + KH_OFF);
    __nv_bfloat16* Kl = (__nv_bfloat16*)(smem + KL_OFF);
    __nv_bfloat16* Vh = (__nv_bfloat16*)(smem + VH_OFF);
    __nv_bfloat16* Vl = (__nv_bfloat16*)(smem + VL_OFF);
    __nv_bfloat16* Eh = (__nv_bfloat16*)(smem + EH_OFF);
    __nv_bfloat16* El = (__nv_bfloat16*)(smem + EL_OFF);
    float* sS   = (float*)(smem + SS_OFF);
    float* sCs  = (float*)(smem + SCS_OFF);
    float* sInv = (float*)(smem + SINV_OFF);
    const u32 sbase = (u32)__cvta_generic_to_shared(smem);

    const int bh = blockIdx.y;
    const int ib = 15 - (int)blockIdx.x;
    const int i0 = ib * 64;
    const int rowbase = bh * S_LEN + i0;
    const int tid = threadIdx.x;
    const int wid = tid >> 5, lane = tid & 31;
    const int mrow = 16 * (wid & 3);
    const int n0   = 32 * (wid >> 2);
    const int tx = tid & 15, ty = tid >> 4;
    const int rl = ty << 2, cl = tx << 2;

    // ---- Q prep: split into Qh/Ql ----
    #pragma unroll
    for (int l = 0; l < 4; ++l) {
        int e = tid + l * 256;
        int r = e >> 4, c4 = (e & 15) << 2;
        float4 vv = *(const float4*)(q + (size_t)(rowbase + r) * 64 + c4);
        u32 h0, l0, h1, l1;
        split2(vv.x, vv.y, h0, l0); split2(vv.z, vv.w, h1, l1);
        *(u32*)&Qh[r*TW + c4] = h0; *(u32*)&Qh[r*TW + c4 + 2] = h1;
        *(u32*)&Ql[r*TW + c4] = l0; *(u32*)&Ql[r*TW + c4 + 2] = l1;
    }
    if (tid < 64) { sS[tid] = 0.f; sCs[tid] = 0.f; }

    const int r1 = mrow + (lane >> 2), r2 = r1 + 8;
    const int i1 = i0 + r1, i2 = i0 + r2;
    const size_t prow1 = (size_t)(rowbase + r1) * PSTR;
    const size_t prow2 = (size_t)(rowbase + r2) * PSTR;
    const size_t wrow1 = (size_t)(rowbase + r1) * S_LEN;
    const size_t wrow2 = (size_t)(rowbase + r2) * S_LEN;

    const int lA_r = (lane & 7) + ((lane >> 3) & 1) * 8;
    const int lA_c = ((lane >> 4) & 1) * 8;
    const int lB_r = (lane & 7);
    const int lB_c = ((lane >> 3) & 1) * 8;
    const int lBt_r = (lane & 7) + ((lane >> 3) & 1) * 8;

    float accO[4][4] = {};

    // ================= pass1 =================
    for (int jb = 0; jb <= ib; ++jb) {
        const int j0 = jb * 64;
        __syncthreads();   // (1) previous tile's mma reads done

        // load pre-split K,V bf16 tiles (no conversion math)
        #pragma unroll
        for (int l = 0; l < 2; ++l) {
            int e = tid + l * 256;
            int r = e >> 3, c8 = (e & 7) << 3;
            const size_t ga = (size_t)(bh*S_LEN + j0 + r)*64 + c8;
            *(uint4*)&Kh[r*TW + c8] = *(const uint4*)&gKh[ga];
            *(uint4*)&Kl[r*TW + c8] = *(const uint4*)&gKl[ga];
            *(uint4*)&Vh[r*TW + c8] = *(const uint4*)&gVh[ga];
            *(uint4*)&Vl[r*TW + c8] = *(const uint4*)&gVl[ga];
        }
        __syncthreads();   // (2) tiles ready

        // ---- QK^T via mma ----
        float accC[4][4] = {};
        #pragma unroll
        for (int ks = 0; ks < 4; ++ks) {
            u32 ah[4], al[4], bh2[2], bl2[2];
            ldmx4(ah, sbase + QH_OFF + (u32)((mrow + lA_r)*TW + ks*16 + lA_c)*2);
            ldmx4(al, sbase + QL_OFF + (u32)((mrow + lA_r)*TW + ks*16 + lA_c)*2);
            #pragma unroll
            for (int nt = 0; nt < 4; ++nt) {
                ldmx2(bh2, sbase + KH_OFF + (u32)((n0 + 8*nt + lB_r)*TW + ks*16 + lB_c)*2);
                ldmx2(bl2, sbase + KL_OFF + (u32)((n0 + 8*nt + lB_r)*TW + ks*16 + lB_c)*2);
                mma16816(accC[nt], ah, bh2);
                mma16816(accC[nt], ah, bl2);
                mma16816(accC[nt], al, bh2);
            }
        }

        // ---- bias + mask + exp + rowsum + scatter + E->bf16 smem ----
        float s1 = 0.f, s2 = 0.f;
        #pragma unroll
        for (int nt = 0; nt < 4; ++nt) {
            const int jl = n0 + 8*nt + 2*(lane & 3);
            const int j  = j0 + jl;
            {
                int p0c = j - i1 + 512;   if (p0c < 0) p0c = 0;
                int p1c = j + 1 - i1 + 512; if (p1c < 0) p1c = 0;
                float l0 = accC[nt][0] + g_P[prow1 + p0c];
                float l1 = accC[nt][1] + g_P[prow1 + p1c];
                if (j     > i1) l0 = -1e30f;
                if (j + 1 > i1) l1 = -1e30f;
                float e0 = __expf(l0), e1 = __expf(l1);
                s1 += e0 + e1;
                int mm = i1 - j;
                if (mm >= 0) {
                    if (mm < 512) g_C[prow1 + mm] = e0;
                    else { atomicAdd(&sCs[r1], e0); wbuf[wrow1 + j] = e0; }
                }
                if (mm - 1 >= 0) {
                    if (mm - 1 < 512) g_C[prow1 + mm - 1] = e1;
                    else { atomicAdd(&sCs[r1], e1); wbuf[wrow1 + j + 1] = e1; }
                }
                u32 hh, ll; split2(e0, e1, hh, ll);
                *(u32*)&Eh[r1*TW + jl] = hh;
                *(u32*)&El[r1*TW + jl] = ll;
            }
            {
                int p0c = j - i2 + 512;   if (p0c < 0) p0c = 0;
                int p1c = j + 1 - i2 + 512; if (p1c < 0) p1c = 0;
                float l0 = accC[nt][2] + g_P[prow2 + p0c];
                float l1 = accC[nt][3] + g_P[prow2 + p1c];
                if (j     > i2) l0 = -1e30f;
                if (j + 1 > i2) l1 = -1e30f;
                float e0 = __expf(l0), e1 = __expf(l1);
                s2 += e0 + e1;
                int mm = i2 - j;
                if (mm >= 0) {
                    if (mm < 512) g_C[prow2 + mm] = e0;
                    else { atomicAdd(&sCs[r2], e0); wbuf[wrow2 + j] = e0; }
                }
                if (mm - 1 >= 0) {
                    if (mm - 1 < 512) g_C[prow2 + mm - 1] = e1;
                    else { atomicAdd(&sCs[r2], e1); wbuf[wrow2 + j + 1] = e1; }
                }
                u32 hh, ll; split2(e0, e1, hh, ll);
                *(u32*)&Eh[r2*TW + jl] = hh;
                *(u32*)&El[r2*TW + jl] = ll;
            }
        }
        s1 += __shfl_xor_sync(0xffffffffu, s1, 1);
        s1 += __shfl_xor_sync(0xffffffffu, s1, 2);
        s2 += __shfl_xor_sync(0xffffffffu, s2, 1);
        s2 += __shfl_xor_sync(0xffffffffu, s2, 2);
        if ((lane & 3) == 0) { atomicAdd(&sS[r1], s1); atomicAdd(&sS[r2], s2); }

        __syncthreads();   // (3) E tiles ready

        // ---- accO += E @ V via mma ----
        #pragma unroll
        for (int ks = 0; ks < 4; ++ks) {
            u32 ah[4], al[4], bh2[2], bl2[2];
            ldmx4(ah, sbase + EH_OFF + (u32)((mrow + lA_r)*TW + ks*16 + lA_c)*2);
            ldmx4(al, sbase + EL_OFF + (u32)((mrow + lA_r)*TW + ks*16 + lA_c)*2);
            #pragma unroll
            for (int nt = 0; nt < 4; ++nt) {
                ldmx2t(bh2, sbase + VH_OFF + (u32)((ks*16 + lBt_r)*TW + n0 + 8*nt)*2);
                ldmx2t(bl2, sbase + VL_OFF + (u32)((ks*16 + lBt_r)*TW + n0 + 8*nt)*2);
                mma16816(accO[nt], ah, bh2);
                mma16816(accO[nt], ah, bl2);
                mma16816(accO[nt], al, bh2);
            }
        }
    }

    __syncthreads();
    if (tid < 64) {
        sInv[tid] = 1.0f / sS[tid];
        g_C[(size_t)(rowbase + tid) * PSTR + 512] = sCs[tid];
    }
    // dump accO fragments -> sOut (fp32 64x68, aliases Kh/Kl region)
    float* sOut = (float*)(smem + KH_OFF);
    #pragma unroll
    for (int nt = 0; nt < 4; ++nt) {
        const int c = n0 + 8*nt + 2*(lane & 3);
        sOut[r1*68 + c]     = accO[nt][0];
        sOut[r1*68 + c + 1] = accO[nt][1];
        sOut[r2*68 + c]     = accO[nt][2];
        sOut[r2*68 + c + 1] = accO[nt][3];
    }

    // ---- D-phase (scalar FFMA2): accD += C_E @ Wv_rev, L2-hot g_C ----
    float* sCT = (float*)(smem + VH_OFF);   // [m][r] 64x68
    float* sB  = (float*)(smem + EH_OFF);   // [m][d] 64x68
    ull accD2[4][2] = {};
    const int mEnd = min(NP, i0 + 64);
    for (int m0 = 0; m0 < mEnd; m0 += 64) {
        __syncthreads();
        #pragma unroll
        for (int l = 0; l < 4; ++l) {
            int e = tid + l * 256;
            int r = e >> 4, c4 = (e & 15) << 2;
            const int mb = m0 + c4;
            const int irow = i0 + r;
            float4 vv = make_float4(0.f,0.f,0.f,0.f);
            if (mb <= 512)
                vv = *(const float4*)(g_C + (size_t)(rowbase + r)*PSTR + mb);
            float comp[4] = {vv.x, vv.y, vv.z, vv.w};
            #pragma unroll
            for (int t = 0; t < 4; ++t) {
                const int m = mb + t;
                const bool ok = (m < 512) ? (m <= irow) : (m == 512);
                sCT[(c4 + t)*68 + r] = ok ? comp[t] : 0.f;
            }
        }
        #pragma unroll
        for (int l = 0; l < 4; ++l) {
            int e = tid + l * 256;
            int mm = e >> 4, c4 = (e & 15) << 2;
            const int m = m0 + mm;
            float4 vv = make_float4(0.f,0.f,0.f,0.f);
            if (m <= 512) vv = *(const float4*)(Wv + (size_t)(512 - m)*64 + c4);
            *(float4*)&sB[mm*68 + c4] = vv;
        }
        __syncthreads();
        #pragma unroll 8
        for (int m = 0; m < 64; ++m) {
            float4 a4 = *(const float4*)&sCT[m*68 + rl];
            ull b01 = *(const ull*)&sB[m*68 + cl];
            ull b23 = *(const ull*)&sB[m*68 + cl + 2];
            ull d0 = dup2(a4.x), d1 = dup2(a4.y), d2 = dup2(a4.z), d3 = dup2(a4.w);
            ffma2(accD2[0][0], d0, b01); ffma2(accD2[0][1], d0, b23);
            ffma2(accD2[1][0], d1, b01); ffma2(accD2[1][1], d1, b23);
            ffma2(accD2[2][0], d2, b01); ffma2(accD2[2][1], d2, b23);
            ffma2(accD2[3][0], d3, b01); ffma2(accD2[3][1], d3, b23);
        }
    }

    // final output: (E@V + C@Wv_rev) * sInv
    #pragma unroll
    for (int ri = 0; ri < 4; ++ri) {
        float d0, d1, d2, d3;
        unpk(d0, d1, accD2[ri][0]);
        unpk(d2, d3, accD2[ri][1]);
        float4 o = *(const float4*)&sOut[(rl + ri)*68 + cl];
        const float inv = sInv[rl + ri];
        *(float4*)(outp + (size_t)(rowbase + rl + ri) * 64 + cl)
            = make_float4((o.x + d0)*inv, (o.y + d1)*inv, (o.z + d2)*inv, (o.w + d3)*inv);
    }

    // ---- pass2: weights from g_C (L2-hot) ----
    for (int jb = 0; jb < 16; ++jb) {
        const int j0 = jb * 64;
        if (jb > ib) {
            const float4 z = make_float4(0.f, 0.f, 0.f, 0.f);
            for (int e = tid; e < 1024; e += 256) {
                int r = e >> 4, c4 = (e & 15) << 2;
                *(float4*)(wbuf + (size_t)(rowbase + r) * S_LEN + j0 + c4) = z;
            }
            continue;
        }
        for (int e = tid; e < 1024; e += 256) {
            int r = e >> 4, c4 = (e & 15) << 2;
            const int i = i0 + r;
            const size_t row = (size_t)(rowbase + r);
            const size_t addr = row * S_LEN + j0 + c4;
            const size_t prow = row * PSTR;
            const float f = sInv[r];
            float w[4];
            #pragma unroll
            for (int t = 0; t < 4; ++t) {
                const int j = j0 + c4 + t;
                const int mm = i - j;
                float eV = 0.f;
                if (mm >= 0) {
                    if (mm < 512) eV = g_C[prow + mm];
                    else          eV = wbuf[addr + t];
                }
                w[t] = eV * f;
            }
            *(float4*)(wbuf + addr) = make_float4(w[0], w[1], w[2], w[3]);
        }
    }
}

// ---------------------------------------------------------------------------
extern "C" void kernel_launch(void* const* d_in, const int* in_sizes, int n_in,
                              void* d_out, int out_size) {
    const float* q  = (const float*)d_in[0];
    const float* k  = (const float*)d_in[1];
    const float* v  = (const float*)d_in[2];
    const float* Wk = (const float*)d_in[3];
    const float* Wv = (const float*)d_in[4];

    float* outp = (float*)d_out;            // (B,H,S,D)
    float* wbuf = outp + OUT_ELEMS;         // (B,H,S,S) weights

    static bool attrs_set = false;
    if (!attrs_set) {
        cudaFuncSetAttribute(kernA,   cudaFuncAttributeMaxDynamicSharedMemorySize, SMEM_A);
        cudaFuncSetAttribute(kernBCD, cudaFuncAttributeMaxDynamicSharedMemorySize, SMEM_BCD);
        attrs_set = true;
    }
    kernSplit<<<4096, 256>>>(k, v);
    kernP512<<<256, 256>>>(q, Wk);
    kernA<<<dim3(1024, 4), 256, SMEM_A>>>(q, Wk);
    kernBCD<<<dim3(16, 64), 256, SMEM_BCD>>>(q, Wv, wbuf, outp);
}

// round 14
// speedup vs baseline: 1.7423x; 1.1225x over previous
#include <cuda_runtime.h>
#include <cuda_bf16.h>

#define S_LEN 1024
#define NP 513
#define PSTR 516
#define OUT_ELEMS 4194304
#define NROWS 65536
#define TW 72   // bf16 smem row stride (elements)

typedef unsigned long long ull;
typedef unsigned int u32;

__device__ float g_P[(size_t)NROWS * PSTR];   // P[row,p] = q[row]·Wk[p]
__device__ u32   g_Cp[(size_t)NROWS * PSTR];  // packed bf16 hi/lo of shifted E
__device__ __nv_bfloat16 gKh[OUT_ELEMS], gKl[OUT_ELEMS];
__device__ __nv_bfloat16 gVh[OUT_ELEMS], gVl[OUT_ELEMS];

// smem byte offsets for kernBCD (E aliases K; C/Wv chunks alias K/V)
#define QH_OFF 0
#define QL_OFF 9216
#define KH_OFF 18432
#define KL_OFF 27648
#define VH_OFF 36864
#define VL_OFF 46080
#define SS_OFF 55296
#define SCS_OFF 55552
#define SINV_OFF 55808
#define SWV0_OFF 56064
#define SMEM_BCD 56320

// smem byte offsets for kernA (tensor)
#define AQH_OFF 0
#define AQL_OFF 9216
#define AWH_OFF 18432
#define AWL_OFF 36864
#define SMEM_A 55296

// ---- tensor helpers ----
__device__ __forceinline__ void ldmx4(u32* r, u32 addr) {
    asm volatile("ldmatrix.sync.aligned.m8n8.x4.shared.b16 {%0,%1,%2,%3}, [%4];"
        : "=r"(r[0]), "=r"(r[1]), "=r"(r[2]), "=r"(r[3]) : "r"(addr));
}
__device__ __forceinline__ void ldmx2(u32* r, u32 addr) {
    asm volatile("ldmatrix.sync.aligned.m8n8.x2.shared.b16 {%0,%1}, [%2];"
        : "=r"(r[0]), "=r"(r[1]) : "r"(addr));
}
__device__ __forceinline__ void ldmx2t(u32* r, u32 addr) {
    asm volatile("ldmatrix.sync.aligned.m8n8.x2.trans.shared.b16 {%0,%1}, [%2];"
        : "=r"(r[0]), "=r"(r[1]) : "r"(addr));
}
__device__ __forceinline__ void mma16816(float* c, const u32* a, const u32* b) {
    asm volatile("mma.sync.aligned.m16n8k16.row.col.f32.bf16.bf16.f32 "
        "{%0,%1,%2,%3}, {%4,%5,%6,%7}, {%8,%9}, {%0,%1,%2,%3};"
        : "+f"(c[0]), "+f"(c[1]), "+f"(c[2]), "+f"(c[3])
        : "r"(a[0]), "r"(a[1]), "r"(a[2]), "r"(a[3]), "r"(b[0]), "r"(b[1]));
}
__device__ __forceinline__ void split2(float x, float y, u32& h, u32& l) {
    __nv_bfloat16 hx = __float2bfloat16(x), hy = __float2bfloat16(y);
    __nv_bfloat162 hh; hh.x = hx; hh.y = hy;
    __nv_bfloat162 ll;
    ll.x = __float2bfloat16(x - __bfloat162float(hx));
    ll.y = __float2bfloat16(y - __bfloat162float(hy));
    h = *(u32*)&hh; l = *(u32*)&ll;
}

// ---------------------------------------------------------------------------
// kernSplit: K,V fp32 -> global bf16 hi/lo (once)
// ---------------------------------------------------------------------------
__global__ void __launch_bounds__(256) kernSplit(const float* __restrict__ k,
                                                 const float* __restrict__ v) {
    const int idx = (blockIdx.x * 256 + threadIdx.x) * 4;
    float4 kv = *(const float4*)(k + idx);
    u32 h0, l0, h1, l1;
    split2(kv.x, kv.y, h0, l0); split2(kv.z, kv.w, h1, l1);
    *(uint2*)&gKh[idx] = make_uint2(h0, h1);
    *(uint2*)&gKl[idx] = make_uint2(l0, l1);
    float4 vv = *(const float4*)(v + idx);
    split2(vv.x, vv.y, h0, l0); split2(vv.z, vv.w, h1, l1);
    *(uint2*)&gVh[idx] = make_uint2(h0, h1);
    *(uint2*)&gVl[idx] = make_uint2(l0, l1);
}

// ---------------------------------------------------------------------------
// kernP512: g_P[row, 512] = q[row] · Wk[512]  (fp32 exact; diagonal bias)
// ---------------------------------------------------------------------------
__global__ void __launch_bounds__(256) kernP512(const float* __restrict__ q,
                                                const float* __restrict__ Wk) {
    __shared__ float w512[64];
    const int tid = threadIdx.x;
    if (tid < 64) w512[tid] = Wk[(size_t)512 * 64 + tid];
    __syncthreads();
    const int row = blockIdx.x * 256 + tid;
    const float* qr = q + (size_t)row * 64;
    float s = 0.f;
    #pragma unroll
    for (int c4 = 0; c4 < 64; c4 += 4) {
        float4 vv = *(const float4*)(qr + c4);
        s += vv.x * w512[c4] + vv.y * w512[c4+1] + vv.z * w512[c4+2] + vv.w * w512[c4+3];
    }
    g_P[(size_t)row * PSTR + 512] = s;
}

// ---------------------------------------------------------------------------
// Kernel A (tensor): P = Q @ Wk^T for p in [0,512), 64x128 tiles, bf16 3-split
// ---------------------------------------------------------------------------
__global__ void __launch_bounds__(256) kernA(const float* __restrict__ q,
                                             const float* __restrict__ Wk) {
    const int r0 = blockIdx.x * 64;
    const int p0 = blockIdx.y * 128;
    const int i0 = r0 & (S_LEN - 1);
    if (p0 + 127 < 449 - i0) return;
    extern __shared__ char smemA[];
    __nv_bfloat16* Qh = (__nv_bfloat16*)(smemA + AQH_OFF);
    __nv_bfloat16* Ql = (__nv_bfloat16*)(smemA + AQL_OFF);
    __nv_bfloat16* Wh = (__nv_bfloat16*)(smemA + AWH_OFF);
    __nv_bfloat16* Wl = (__nv_bfloat16*)(smemA + AWL_OFF);
    const u32 sbase = (u32)__cvta_generic_to_shared(smemA);
    const int tid = threadIdx.x;
    const int wid = tid >> 5, lane = tid & 31;

    #pragma unroll
    for (int l = 0; l < 4; ++l) {
        int e = tid + l * 256;
        int r = e >> 4, c4 = (e & 15) << 2;
        float4 vv = *(const float4*)(q + (size_t)(r0 + r) * 64 + c4);
        u32 h0, l0, h1, l1;
        split2(vv.x, vv.y, h0, l0); split2(vv.z, vv.w, h1, l1);
        *(u32*)&Qh[r*TW + c4] = h0; *(u32*)&Qh[r*TW + c4 + 2] = h1;
        *(u32*)&Ql[r*TW + c4] = l0; *(u32*)&Ql[r*TW + c4 + 2] = l1;
    }
    #pragma unroll
    for (int l = 0; l < 8; ++l) {
        int e = tid + l * 256;
        int r = e >> 4, c4 = (e & 15) << 2;
        float4 vv = *(const float4*)(Wk + (size_t)(p0 + r) * 64 + c4);
        u32 h0, l0, h1, l1;
        split2(vv.x, vv.y, h0, l0); split2(vv.z, vv.w, h1, l1);
        *(u32*)&Wh[r*TW + c4] = h0; *(u32*)&Wh[r*TW + c4 + 2] = h1;
        *(u32*)&Wl[r*TW + c4] = l0; *(u32*)&Wl[r*TW + c4 + 2] = l1;
    }
    __syncthreads();

    const int mrow = 16 * (wid & 3);
    const int n0   = 64 * (wid >> 2);
    const int lA_r = (lane & 7) + ((lane >> 3) & 1) * 8;
    const int lA_c = ((lane >> 4) & 1) * 8;
    const int lB_r = (lane & 7);
    const int lB_c = ((lane >> 3) & 1) * 8;

    float accP[8][4] = {};
    #pragma unroll
    for (int ks = 0; ks < 4; ++ks) {
        u32 ah[4], al[4], bh2[2], bl2[2];
        ldmx4(ah, sbase + AQH_OFF + (u32)((mrow + lA_r)*TW + ks*16 + lA_c)*2);
        ldmx4(al, sbase + AQL_OFF + (u32)((mrow + lA_r)*TW + ks*16 + lA_c)*2);
        #pragma unroll
        for (int nt = 0; nt < 8; ++nt) {
            ldmx2(bh2, sbase + AWH_OFF + (u32)((n0 + 8*nt + lB_r)*TW + ks*16 + lB_c)*2);
            ldmx2(bl2, sbase + AWL_OFF + (u32)((n0 + 8*nt + lB_r)*TW + ks*16 + lB_c)*2);
            mma16816(accP[nt], ah, bh2);
            mma16816(accP[nt], ah, bl2);
            mma16816(accP[nt], al, bh2);
        }
    }

    const int r1 = mrow + (lane >> 2), r2 = r1 + 8;
    const size_t row1 = (size_t)(r0 + r1) * PSTR;
    const size_t row2 = (size_t)(r0 + r2) * PSTR;
    #pragma unroll
    for (int nt = 0; nt < 8; ++nt) {
        const int p = p0 + n0 + 8*nt + 2*(lane & 3);
        *(float2*)(g_P + row1 + p) = make_float2(accP[nt][0], accP[nt][1]);
        *(float2*)(g_P + row2 + p) = make_float2(accP[nt][2], accP[nt][3]);
    }
}

// ---------------------------------------------------------------------------
// Fused B+C+D: all three GEMMs on tensor cores; packed bf16 hi/lo g_Cp.
// ---------------------------------------------------------------------------
__global__ void __launch_bounds__(256) kernBCD(const float* __restrict__ q,
                                               const float* __restrict__ Wv,
                                               float* __restrict__ wbuf,
                                               float* __restrict__ outp) {
    extern __shared__ char smem[];
    __nv_bfloat16* Qh = (__nv_bfloat16*)(smem + QH_OFF);
    __nv_bfloat16* Ql = (__nv_bfloat16*)(smem + QL_OFF);
    __nv_bfloat16* Kh = (__nv_bfloat16*)(smem + KH_OFF);   // K^T; E; C-chunk
    __nv_bfloat16* Kl = (__nv_bfloat16*)(smem + KL_OFF);
    __nv_bfloat16* Vh = (__nv_bfloat16*)(smem + VH_OFF);   // V; Wv-chunk
    __nv_bfloat16* Vl = (__nv_bfloat16*)(smem + VL_OFF);
    float* sS   = (float*)(smem + SS_OFF);
    float* sCs  = (float*)(smem + SCS_OFF);
    float* sInv = (float*)(smem + SINV_OFF);
    float* sWv0 = (float*)(smem + SWV0_OFF);
    const u32 sbase = (u32)__cvta_generic_to_shared(smem);

    const int bh = blockIdx.y;
    const int ib = 15 - (int)blockIdx.x;
    const int i0 = ib * 64;
    const int rowbase = bh * S_LEN + i0;
    const int tid = threadIdx.x;
    const int wid = tid >> 5, lane = tid & 31;
    const int mrow = 16 * (wid & 3);
    const int n0   = 32 * (wid >> 2);

    // ---- Q prep: split into Qh/Ql ----
    #pragma unroll
    for (int l = 0; l < 4; ++l) {
        int e = tid + l * 256;
        int r = e >> 4, c4 = (e & 15) << 2;
        float4 vv = *(const float4*)(q + (size_t)(rowbase + r) * 64 + c4);
        u32 h0, l0, h1, l1;
        split2(vv.x, vv.y, h0, l0); split2(vv.z, vv.w, h1, l1);
        *(u32*)&Qh[r*TW + c4] = h0; *(u32*)&Qh[r*TW + c4 + 2] = h1;
        *(u32*)&Ql[r*TW + c4] = l0; *(u32*)&Ql[r*TW + c4 + 2] = l1;
    }
    if (tid < 64) { sS[tid] = 0.f; sCs[tid] = 0.f; }

    const int r1 = mrow + (lane >> 2), r2 = r1 + 8;
    const int i1 = i0 + r1, i2 = i0 + r2;
    const size_t prow1 = (size_t)(rowbase + r1) * PSTR;
    const size_t prow2 = (size_t)(rowbase + r2) * PSTR;
    const size_t wrow1 = (size_t)(rowbase + r1) * S_LEN;
    const size_t wrow2 = (size_t)(rowbase + r2) * S_LEN;

    const int lA_r = (lane & 7) + ((lane >> 3) & 1) * 8;
    const int lA_c = ((lane >> 4) & 1) * 8;
    const int lB_r = (lane & 7);
    const int lB_c = ((lane >> 3) & 1) * 8;
    const int lBt_r = (lane & 7) + ((lane >> 3) & 1) * 8;

    float accO[4][4] = {};

    // ================= pass1 =================
    for (int jb = 0; jb <= ib; ++jb) {
        const int j0 = jb * 64;
        __syncthreads();   // (1) prev E@V mma done

        // load pre-split K,V bf16 tiles
        #pragma unroll
        for (int l = 0; l < 2; ++l) {
            int e = tid + l * 256;
            int r = e >> 3, c8 = (e & 7) << 3;
            const size_t ga = (size_t)(bh*S_LEN + j0 + r)*64 + c8;
            *(uint4*)&Kh[r*TW + c8] = *(const uint4*)&gKh[ga];
            *(uint4*)&Kl[r*TW + c8] = *(const uint4*)&gKl[ga];
            *(uint4*)&Vh[r*TW + c8] = *(const uint4*)&gVh[ga];
            *(uint4*)&Vl[r*TW + c8] = *(const uint4*)&gVl[ga];
        }
        __syncthreads();   // (2) tiles ready

        // ---- QK^T via mma ----
        float accC[4][4] = {};
        #pragma unroll
        for (int ks = 0; ks < 4; ++ks) {
            u32 ah[4], al[4], bh2[2], bl2[2];
            ldmx4(ah, sbase + QH_OFF + (u32)((mrow + lA_r)*TW + ks*16 + lA_c)*2);
            ldmx4(al, sbase + QL_OFF + (u32)((mrow + lA_r)*TW + ks*16 + lA_c)*2);
            #pragma unroll
            for (int nt = 0; nt < 4; ++nt) {
                ldmx2(bh2, sbase + KH_OFF + (u32)((n0 + 8*nt + lB_r)*TW + ks*16 + lB_c)*2);
                ldmx2(bl2, sbase + KL_OFF + (u32)((n0 + 8*nt + lB_r)*TW + ks*16 + lB_c)*2);
                mma16816(accC[nt], ah, bh2);
                mma16816(accC[nt], ah, bl2);
                mma16816(accC[nt], al, bh2);
            }
        }
        __syncthreads();   // (3) K reads done -> E may overwrite Kh/Kl

        // ---- bias + mask + exp + rowsum + packed scatter + E->smem ----
        float s1 = 0.f, s2 = 0.f;
        #pragma unroll
        for (int nt = 0; nt < 4; ++nt) {
            const int jl = n0 + 8*nt + 2*(lane & 3);
            const int j  = j0 + jl;
            {
                int p0c = j - i1 + 512;   if (p0c < 0) p0c = 0;
                int p1c = j + 1 - i1 + 512; if (p1c < 0) p1c = 0;
                float l0 = accC[nt][0] + g_P[prow1 + p0c];
                float l1 = accC[nt][1] + g_P[prow1 + p1c];
                if (j     > i1) l0 = -1e30f;
                if (j + 1 > i1) l1 = -1e30f;
                float e0 = __expf(l0), e1 = __expf(l1);
                s1 += e0 + e1;
                u32 hh, ll; split2(e0, e1, hh, ll);
                *(u32*)&Kh[r1*TW + jl] = hh;
                *(u32*)&Kl[r1*TW + jl] = ll;
                const u32 pk0 = (hh & 0xFFFFu) | (ll << 16);
                const u32 pk1 = (hh >> 16) | (ll & 0xFFFF0000u);
                int mm = i1 - j;
                if (mm >= 0) {
                    if (mm < 512) g_Cp[prow1 + mm] = pk0;
                    else { atomicAdd(&sCs[r1], e0); wbuf[wrow1 + j] = e0; }
                }
                if (mm - 1 >= 0) {
                    if (mm - 1 < 512) g_Cp[prow1 + mm - 1] = pk1;
                    else { atomicAdd(&sCs[r1], e1); wbuf[wrow1 + j + 1] = e1; }
                }
            }
            {
                int p0c = j - i2 + 512;   if (p0c < 0) p0c = 0;
                int p1c = j + 1 - i2 + 512; if (p1c < 0) p1c = 0;
                float l0 = accC[nt][2] + g_P[prow2 + p0c];
                float l1 = accC[nt][3] + g_P[prow2 + p1c];
                if (j     > i2) l0 = -1e30f;
                if (j + 1 > i2) l1 = -1e30f;
                float e0 = __expf(l0), e1 = __expf(l1);
                s2 += e0 + e1;
                u32 hh, ll; split2(e0, e1, hh, ll);
                *(u32*)&Kh[r2*TW + jl] = hh;
                *(u32*)&Kl[r2*TW + jl] = ll;
                const u32 pk0 = (hh & 0xFFFFu) | (ll << 16);
                const u32 pk1 = (hh >> 16) | (ll & 0xFFFF0000u);
                int mm = i2 - j;
                if (mm >= 0) {
                    if (mm < 512) g_Cp[prow2 + mm] = pk0;
                    else { atomicAdd(&sCs[r2], e0); wbuf[wrow2 + j] = e0; }
                }
                if (mm - 1 >= 0) {
                    if (mm - 1 < 512) g_Cp[prow2 + mm - 1] = pk1;
                    else { atomicAdd(&sCs[r2], e1); wbuf[wrow2 + j + 1] = e1; }
                }
            }
        }
        s1 += __shfl_xor_sync(0xffffffffu, s1, 1);
        s1 += __shfl_xor_sync(0xffffffffu, s1, 2);
        s2 += __shfl_xor_sync(0xffffffffu, s2, 1);
        s2 += __shfl_xor_sync(0xffffffffu, s2, 2);
        if ((lane & 3) == 0) { atomicAdd(&sS[r1], s1); atomicAdd(&sS[r2], s2); }

        __syncthreads();   // (4) E tiles ready

        // ---- accO += E @ V via mma (E aliased in Kh/Kl) ----
        #pragma unroll
        for (int ks = 0; ks < 4; ++ks) {
            u32 ah[4], al[4], bh2[2], bl2[2];
            ldmx4(ah, sbase + KH_OFF + (u32)((mrow + lA_r)*TW + ks*16 + lA_c)*2);
            ldmx4(al, sbase + KL_OFF + (u32)((mrow + lA_r)*TW + ks*16 + lA_c)*2);
            #pragma unroll
            for (int nt = 0; nt < 4; ++nt) {
                ldmx2t(bh2, sbase + VH_OFF + (u32)((ks*16 + lBt_r)*TW + n0 + 8*nt)*2);
                ldmx2t(bl2, sbase + VL_OFF + (u32)((ks*16 + lBt_r)*TW + n0 + 8*nt)*2);
                mma16816(accO[nt], ah, bh2);
                mma16816(accO[nt], ah, bl2);
                mma16816(accO[nt], al, bh2);
            }
        }
    }

    __syncthreads();
    if (tid < 64) {
        sInv[tid] = 1.0f / sS[tid];
        sWv0[tid] = Wv[tid];   // Wv_rev[512] = Wv[0][:]
    }

    // ---- D-phase (mma): accD += C_E @ Wv_rev, m in [0, min(512, i0+64)) ----
    float accD[4][4] = {};
    const int mEndD = min(512, i0 + 64);
    for (int m0 = 0; m0 < mEndD; m0 += 64) {
        __syncthreads();   // buffers free
        // C chunk: unpack g_Cp -> Ch/Cl (Kh/Kl region), mask m > irow
        #pragma unroll
        for (int l = 0; l < 4; ++l) {
            int e = tid + l * 256;
            int r = e >> 4, m4 = (e & 15) << 2;
            const int irow = i0 + r;
            const int mb = m0 + m4;
            uint4 pp = *(const uint4*)(g_Cp + (size_t)(rowbase + r)*PSTR + mb);
            u32 pa[4] = {pp.x, pp.y, pp.z, pp.w};
            #pragma unroll
            for (int t = 0; t < 4; ++t)
                if (mb + t > irow) pa[t] = 0;
            *(u32*)&Kh[r*TW + m4]     = (pa[0] & 0xFFFFu) | ((pa[1] & 0xFFFFu) << 16);
            *(u32*)&Kh[r*TW + m4 + 2] = (pa[2] & 0xFFFFu) | ((pa[3] & 0xFFFFu) << 16);
            *(u32*)&Kl[r*TW + m4]     = (pa[0] >> 16) | (pa[1] & 0xFFFF0000u);
            *(u32*)&Kl[r*TW + m4 + 2] = (pa[2] >> 16) | (pa[3] & 0xFFFF0000u);
        }
        // Wv chunk: split fp32 -> Vh/Vl region ([m][d])
        #pragma unroll
        for (int l = 0; l < 4; ++l) {
            int e = tid + l * 256;
            int mr = e >> 4, c4 = (e & 15) << 2;
            const int m = m0 + mr;   // <= 511
            float4 vv = *(const float4*)(Wv + (size_t)(512 - m)*64 + c4);
            u32 h0, l0, h1, l1;
            split2(vv.x, vv.y, h0, l0); split2(vv.z, vv.w, h1, l1);
            *(u32*)&Vh[mr*TW + c4] = h0; *(u32*)&Vh[mr*TW + c4 + 2] = h1;
            *(u32*)&Vl[mr*TW + c4] = l0; *(u32*)&Vl[mr*TW + c4 + 2] = l1;
        }
        __syncthreads();
        #pragma unroll
        for (int ks = 0; ks < 4; ++ks) {
            u32 ah[4], al[4], bh2[2], bl2[2];
            ldmx4(ah, sbase + KH_OFF + (u32)((mrow + lA_r)*TW + ks*16 + lA_c)*2);
            ldmx4(al, sbase + KL_OFF + (u32)((mrow + lA_r)*TW + ks*16 + lA_c)*2);
            #pragma unroll
            for (int nt = 0; nt < 4; ++nt) {
                ldmx2t(bh2, sbase + VH_OFF + (u32)((ks*16 + lBt_r)*TW + n0 + 8*nt)*2);
                ldmx2t(bl2, sbase + VL_OFF + (u32)((ks*16 + lBt_r)*TW + n0 + 8*nt)*2);
                mma16816(accD[nt], ah, bh2);
                mma16816(accD[nt], ah, bl2);
                mma16816(accD[nt], al, bh2);
            }
        }
    }
    __syncthreads();   // sInv/sCs/sWv0 stable, buffers quiesced

    // ---- final output directly from fragments ----
    {
        const float inv1 = sInv[r1], inv2 = sInv[r2];
        const float cs1 = sCs[r1],  cs2 = sCs[r2];
        #pragma unroll
        for (int nt = 0; nt < 4; ++nt) {
            const int c = n0 + 8*nt + 2*(lane & 3);
            const float w00 = (accO[nt][0] + accD[nt][0] + cs1*sWv0[c])   * inv1;
            const float w01 = (accO[nt][1] + accD[nt][1] + cs1*sWv0[c+1]) * inv1;
            const float w10 = (accO[nt][2] + accD[nt][2] + cs2*sWv0[c])   * inv2;
            const float w11 = (accO[nt][3] + accD[nt][3] + cs2*sWv0[c+1]) * inv2;
            *(float2*)(outp + (size_t)(rowbase + r1)*64 + c) = make_float2(w00, w01);
            *(float2*)(outp + (size_t)(rowbase + r2)*64 + c) = make_float2(w10, w11);
        }
    }

    // ---- pass2: weights from g_Cp (unpack hi+lo) ----
    for (int jb = 0; jb < 16; ++jb) {
        const int j0 = jb * 64;
        if (jb > ib) {
            const float4 z = make_float4(0.f, 0.f, 0.f, 0.f);
            for (int e = tid; e < 1024; e += 256) {
                int r = e >> 4, c4 = (e & 15) << 2;
                *(float4*)(wbuf + (size_t)(rowbase + r) * S_LEN + j0 + c4) = z;
            }
            continue;
        }
        for (int e = tid; e < 1024; e += 256) {
            int r = e >> 4, c4 = (e & 15) << 2;
            const int i = i0 + r;
            const size_t row = (size_t)(rowbase + r);
            const size_t addr = row * S_LEN + j0 + c4;
            const size_t prow = row * PSTR;
            const float f = sInv[r];
            float w[4];
            #pragma unroll
            for (int t = 0; t < 4; ++t) {
                const int j = j0 + c4 + t;
                const int mm = i - j;
                float eV = 0.f;
                if (mm >= 0) {
                    if (mm < 512) {
                        const u32 p = g_Cp[prow + mm];
                        eV = __uint_as_float(p << 16) + __uint_as_float(p & 0xFFFF0000u);
                    } else {
                        eV = wbuf[addr + t];   // raw E written in pass1
                    }
                }
                w[t] = eV * f;
            }
            *(float4*)(wbuf + addr) = make_float4(w[0], w[1], w[2], w[3]);
        }
    }
}

// ---------------------------------------------------------------------------
extern "C" void kernel_launch(void* const* d_in, const int* in_sizes, int n_in,
                              void* d_out, int out_size) {
    const float* q  = (const float*)d_in[0];
    const float* k  = (const float*)d_in[1];
    const float* v  = (const float*)d_in[2];
    const float* Wk = (const float*)d_in[3];
    const float* Wv = (const float*)d_in[4];

    float* outp = (float*)d_out;            // (B,H,S,D)
    float* wbuf = outp + OUT_ELEMS;         // (B,H,S,S) weights

    static bool attrs_set = false;
    if (!attrs_set) {
        cudaFuncSetAttribute(kernA,   cudaFuncAttributeMaxDynamicSharedMemorySize, SMEM_A);
        cudaFuncSetAttribute(kernBCD, cudaFuncAttributeMaxDynamicSharedMemorySize, SMEM_BCD);
        attrs_set = true;
    }
    kernSplit<<<4096, 256>>>(k, v);
    kernP512<<<256, 256>>>(q, Wk);
    kernA<<<dim3(1024, 4), 256, SMEM_A>>>(q, Wk);
    kernBCD<<<dim3(16, 64), 256, SMEM_BCD>>>(q, Wv, wbuf, outp);
}